// round 3
// baseline (speedup 1.0000x reference)
#include <cuda_runtime.h>
#include <cstdint>

#define D_MODEL    2048
#define D_HIDDEN   2048
#define NUM_EXPERTS  16
#define N_TOKENS   8192

#define BM 128
#define BN 128
#define BK 8
#define KTILES (D_MODEL / BK)

// Scratch (no allocations allowed): per-slot, per-expert token buckets.
__device__ int   g_counts[2][NUM_EXPERTS];
__device__ int   g_bucket[2][NUM_EXPERTS][N_TOKENS];
__device__ float g_gate  [2][NUM_EXPERTS][N_TOKENS];

__global__ void reset_kernel() {
    if (threadIdx.x < 2 * NUM_EXPERTS)
        ((int*)g_counts)[threadIdx.x] = 0;
}

// One block per token: 16 logits, top-2, softmax over the 2, scatter to buckets.
__global__ void router_kernel(const float* __restrict__ x,
                              const float* __restrict__ rw) {
    __shared__ float sx[D_MODEL];
    __shared__ float slog[NUM_EXPERTS];
    const int token = blockIdx.x;
    const int tid   = threadIdx.x;   // 128 threads
    const float4* xr = (const float4*)(x + (size_t)token * D_MODEL);
    for (int i = tid; i < D_MODEL / 4; i += 128)
        ((float4*)sx)[i] = xr[i];
    __syncthreads();

    const int warp = tid >> 5, lane = tid & 31;
    for (int e = warp; e < NUM_EXPERTS; e += 4) {
        const float* w = rw + (size_t)e * D_MODEL;
        float s = 0.f;
#pragma unroll 8
        for (int i = lane; i < D_MODEL; i += 32)
            s += sx[i] * __ldg(w + i);
#pragma unroll
        for (int o = 16; o > 0; o >>= 1)
            s += __shfl_xor_sync(0xffffffffu, s, o);
        if (lane == 0) slog[e] = s;
    }
    __syncthreads();

    if (tid == 0) {
        float l0 = -3.4e38f, l1 = -3.4e38f;
        int e0 = 0, e1 = 0;
#pragma unroll
        for (int e = 0; e < NUM_EXPERTS; e++) {
            float v = slog[e];
            if (v > l0)      { l1 = l0; e1 = e0; l0 = v; e0 = e; }
            else if (v > l1) { l1 = v;  e1 = e; }
        }
        // softmax over the two selected logits (l0 >= l1)
        float g0 = 1.f / (1.f + expf(l1 - l0));
        float g1 = 1.f - g0;
        int p0 = atomicAdd(&g_counts[0][e0], 1);
        g_bucket[0][e0][p0] = token;
        g_gate  [0][e0][p0] = g0;
        int p1 = atomicAdd(&g_counts[1][e1], 1);
        g_bucket[1][e1][p1] = token;
        g_gate  [1][e1][p1] = g1;
    }
}

// Gathered-row SGEMM: C[rows, col0:col0+BN] (+)= gate * (X[rows] @ W[e]).
// SLOT==0 writes, SLOT==1 accumulates. 128x128x8 tiles, 256 threads, 8x8 microtile.
template <int SLOT>
__global__ void __launch_bounds__(256)
moe_gemm(const float* __restrict__ x,
         const float* __restrict__ ew,
         float* __restrict__ out) {
    const int e    = blockIdx.z;
    const int cnt  = g_counts[SLOT][e];
    const int row0 = blockIdx.y * BM;
    if (row0 >= cnt) return;
    const int col0 = blockIdx.x * BN;
    const int tid  = threadIdx.x;

    const float* W = ew + (size_t)e * D_MODEL * D_HIDDEN;

    __shared__ float As[2][BK * BM];   // transposed: As[k][m]
    __shared__ float Bs[2][BK * BN];
    __shared__ int   rows_s[BM];
    __shared__ float gates_s[BM];

    if (tid < BM) {
        int idx = row0 + tid;
        if (idx < cnt) {
            rows_s[tid]  = g_bucket[SLOT][e][idx];
            gates_s[tid] = g_gate[SLOT][e][idx];
        } else {
            rows_s[tid]  = g_bucket[SLOT][e][row0];  // valid clamp row
            gates_s[tid] = 0.f;
        }
    }
    __syncthreads();

    // global load mapping: one float4 of A and one of B per thread per k-tile
    const int a_row = tid >> 1;            // 0..127
    const int a_col = (tid & 1) * 4;       // 0 or 4
    const int b_row = tid >> 5;            // 0..7
    const int b_col = (tid & 31) * 4;      // 0..124

    const float* a_src = x + (size_t)rows_s[a_row] * D_MODEL + a_col;
    const float* b_src = W + (size_t)b_row * D_HIDDEN + col0 + b_col;

    // prologue: tile 0
    float4 av = *(const float4*)a_src;
    float4 bv = *(const float4*)b_src;
    As[0][(a_col + 0) * BM + a_row] = av.x;
    As[0][(a_col + 1) * BM + a_row] = av.y;
    As[0][(a_col + 2) * BM + a_row] = av.z;
    As[0][(a_col + 3) * BM + a_row] = av.w;
    *(float4*)&Bs[0][b_row * BN + b_col] = bv;
    __syncthreads();

    const int tx = tid & 15, ty = tid >> 4;
    float acc[8][8];
#pragma unroll
    for (int i = 0; i < 8; i++)
#pragma unroll
        for (int j = 0; j < 8; j++) acc[i][j] = 0.f;

    int buf = 0;
    for (int kt = 1; kt <= KTILES; kt++) {
        float4 av_n, bv_n;
        if (kt < KTILES) {
            av_n = *(const float4*)(a_src + kt * BK);
            bv_n = *(const float4*)(b_src + (size_t)kt * BK * D_HIDDEN);
        }
        float ar[8], br[8];
#pragma unroll
        for (int k = 0; k < BK; k++) {
            *(float4*)&ar[0] = *(const float4*)&As[buf][k * BM + ty * 4];
            *(float4*)&ar[4] = *(const float4*)&As[buf][k * BM + 64 + ty * 4];
            *(float4*)&br[0] = *(const float4*)&Bs[buf][k * BN + tx * 4];
            *(float4*)&br[4] = *(const float4*)&Bs[buf][k * BN + 64 + tx * 4];
#pragma unroll
            for (int i = 0; i < 8; i++)
#pragma unroll
                for (int j = 0; j < 8; j++)
                    acc[i][j] += ar[i] * br[j];
        }
        if (kt < KTILES) {
            buf ^= 1;
            As[buf][(a_col + 0) * BM + a_row] = av_n.x;
            As[buf][(a_col + 1) * BM + a_row] = av_n.y;
            As[buf][(a_col + 2) * BM + a_row] = av_n.z;
            As[buf][(a_col + 3) * BM + a_row] = av_n.w;
            *(float4*)&Bs[buf][b_row * BN + b_col] = bv_n;
            __syncthreads();
        }
    }

    // epilogue: scale by gate, scatter rows to out
#pragma unroll
    for (int i = 0; i < 8; i++) {
        const int m = (i < 4) ? (ty * 4 + i) : (64 + ty * 4 + (i - 4));
        if (row0 + m < cnt) {
            const int   token = rows_s[m];
            const float g     = gates_s[m];
            float* orow = out + (size_t)token * D_HIDDEN + col0;
            if (SLOT == 0) {
                float4 v0 = make_float4(g * acc[i][0], g * acc[i][1],
                                        g * acc[i][2], g * acc[i][3]);
                float4 v1 = make_float4(g * acc[i][4], g * acc[i][5],
                                        g * acc[i][6], g * acc[i][7]);
                *(float4*)(orow + tx * 4)      = v0;
                *(float4*)(orow + 64 + tx * 4) = v1;
            } else {
                float4 o0 = *(float4*)(orow + tx * 4);
                float4 o1 = *(float4*)(orow + 64 + tx * 4);
                o0.x += g * acc[i][0]; o0.y += g * acc[i][1];
                o0.z += g * acc[i][2]; o0.w += g * acc[i][3];
                o1.x += g * acc[i][4]; o1.y += g * acc[i][5];
                o1.z += g * acc[i][6]; o1.w += g * acc[i][7];
                *(float4*)(orow + tx * 4)      = o0;
                *(float4*)(orow + 64 + tx * 4) = o1;
            }
        }
    }
}

extern "C" void kernel_launch(void* const* d_in, const int* in_sizes, int n_in,
                              void* d_out, int out_size) {
    (void)in_sizes; (void)n_in; (void)out_size;
    const float* x  = (const float*)d_in[0];
    const float* rw = (const float*)d_in[1];
    const float* ew = (const float*)d_in[2];
    float* out = (float*)d_out;

    reset_kernel<<<1, 32>>>();
    router_kernel<<<N_TOKENS, 128>>>(x, rw);

    dim3 grid(D_HIDDEN / BN, N_TOKENS / BM, NUM_EXPERTS);  // (16, 64, 16)
    moe_gemm<0><<<grid, 256>>>(x, ew, out);
    moe_gemm<1><<<grid, 256>>>(x, ew, out);
}

// round 5
// speedup vs baseline: 2.0088x; 2.0088x over previous
#include <cuda_runtime.h>
#include <cuda_bf16.h>
#include <cstdint>

#define D_MODEL    2048
#define D_HIDDEN   2048
#define NUM_EXPERTS  16
#define N_TOKENS   8192

// mma.sync GEMM tile
#define BM 128
#define BN 128
#define BK 32
#define KCHUNKS (D_MODEL / BK)      // 64
#define NTILES  (D_HIDDEN / BN)     // 16

// ---------------- device scratch (no allocations allowed) ----------------
__device__ int   g_counts[2][NUM_EXPERTS];
__device__ int   g_bucket[2][NUM_EXPERTS][N_TOKENS];
__device__ float g_gate  [2][NUM_EXPERTS][N_TOKENS];

__device__ __nv_bfloat16 g_xhi[(size_t)N_TOKENS * D_MODEL];
__device__ __nv_bfloat16 g_xlo[(size_t)N_TOKENS * D_MODEL];
// W transposed to [e][n][k] (K contiguous) so B feeds non-trans ldmatrix
__device__ __nv_bfloat16 g_whi[(size_t)NUM_EXPERTS * D_HIDDEN * D_MODEL];
__device__ __nv_bfloat16 g_wlo[(size_t)NUM_EXPERTS * D_HIDDEN * D_MODEL];

// ---------------- PTX helpers (compute_103-safe: no tcgen05) ----------------
__device__ __forceinline__ uint32_t smem_u32(const void* p) {
    uint32_t a;
    asm("{ .reg .u64 t; cvta.to.shared.u64 t, %1; cvt.u32.u64 %0, t; }"
        : "=r"(a) : "l"(p));
    return a;
}
__device__ __forceinline__ void cp16(uint32_t dst, const void* src) {
    asm volatile("cp.async.cg.shared.global [%0], [%1], 16;\n"
                 :: "r"(dst), "l"(src));
}
#define CP_COMMIT() asm volatile("cp.async.commit_group;" ::: "memory")
#define CP_WAIT0()  asm volatile("cp.async.wait_group 0;" ::: "memory")

__device__ __forceinline__ void ldsm4(uint32_t* r, uint32_t addr) {
    asm volatile("ldmatrix.sync.aligned.m8n8.x4.shared.b16 {%0,%1,%2,%3}, [%4];"
                 : "=r"(r[0]), "=r"(r[1]), "=r"(r[2]), "=r"(r[3]) : "r"(addr));
}
__device__ __forceinline__ void mma_bf16(float* d, const uint32_t* a,
                                         uint32_t b0, uint32_t b1) {
    asm volatile(
        "mma.sync.aligned.m16n8k16.row.col.f32.bf16.bf16.f32 "
        "{%0,%1,%2,%3}, {%4,%5,%6,%7}, {%8,%9}, {%0,%1,%2,%3};"
        : "+f"(d[0]), "+f"(d[1]), "+f"(d[2]), "+f"(d[3])
        : "r"(a[0]), "r"(a[1]), "r"(a[2]), "r"(a[3]), "r"(b0), "r"(b1));
}

// ---------------- small kernels ----------------
__global__ void reset_kernel() {
    if (threadIdx.x < 2 * NUM_EXPERTS)
        ((int*)g_counts)[threadIdx.x] = 0;
}

__global__ void router_kernel(const float* __restrict__ x,
                              const float* __restrict__ rw) {
    __shared__ float sx[D_MODEL];
    __shared__ float slog[NUM_EXPERTS];
    const int token = blockIdx.x;
    const int tid   = threadIdx.x;   // 128
    const float4* xr = (const float4*)(x + (size_t)token * D_MODEL);
    for (int i = tid; i < D_MODEL / 4; i += 128)
        ((float4*)sx)[i] = xr[i];
    __syncthreads();

    const int warp = tid >> 5, lane = tid & 31;
    for (int e = warp; e < NUM_EXPERTS; e += 4) {
        const float* w = rw + (size_t)e * D_MODEL;
        float s = 0.f;
#pragma unroll 8
        for (int i = lane; i < D_MODEL; i += 32)
            s += sx[i] * __ldg(w + i);
#pragma unroll
        for (int o = 16; o > 0; o >>= 1)
            s += __shfl_xor_sync(0xffffffffu, s, o);
        if (lane == 0) slog[e] = s;
    }
    __syncthreads();

    if (tid == 0) {
        float l0 = -3.4e38f, l1 = -3.4e38f;
        int e0 = 0, e1 = 0;
#pragma unroll
        for (int e = 0; e < NUM_EXPERTS; e++) {
            float v = slog[e];
            if (v > l0)      { l1 = l0; e1 = e0; l0 = v; e0 = e; }
            else if (v > l1) { l1 = v;  e1 = e; }
        }
        float g0 = 1.f / (1.f + expf(l1 - l0));
        float g1 = 1.f - g0;
        int p0 = atomicAdd(&g_counts[0][e0], 1);
        g_bucket[0][e0][p0] = token;
        g_gate  [0][e0][p0] = g0;
        int p1 = atomicAdd(&g_counts[1][e1], 1);
        g_bucket[1][e1][p1] = token;
        g_gate  [1][e1][p1] = g1;
    }
}

// fp32 -> bf16 hi/lo split of x
__global__ void convert_x_kernel(const float* __restrict__ x) {
    size_t i = (size_t)blockIdx.x * blockDim.x + threadIdx.x;  // one float4
    float4 v = ((const float4*)x)[i];
    __nv_bfloat16 h[4], l[4];
    float f[4] = {v.x, v.y, v.z, v.w};
#pragma unroll
    for (int q = 0; q < 4; q++) {
        h[q] = __float2bfloat16(f[q]);
        l[q] = __float2bfloat16(f[q] - __bfloat162float(h[q]));
    }
    __nv_bfloat162* dh = (__nv_bfloat162*)g_xhi;
    __nv_bfloat162* dl = (__nv_bfloat162*)g_xlo;
    dh[2 * i]     = __nv_bfloat162{h[0], h[1]};
    dh[2 * i + 1] = __nv_bfloat162{h[2], h[3]};
    dl[2 * i]     = __nv_bfloat162{l[0], l[1]};
    dl[2 * i + 1] = __nv_bfloat162{l[2], l[3]};
}

// W [e][k][n] fp32  ->  transposed bf16 hi/lo [e][n][k]
__global__ void convert_w_kernel(const float* __restrict__ W) {
    __shared__ float t[32][33];
    const int e  = blockIdx.z;
    const int k0 = blockIdx.y * 32;
    const int n0 = blockIdx.x * 32;
    const int tx = threadIdx.x, ty = threadIdx.y;  // 32 x 8
    const float* src = W + (size_t)e * D_MODEL * D_HIDDEN;
#pragma unroll
    for (int r = ty; r < 32; r += 8)
        t[r][tx] = src[(size_t)(k0 + r) * D_HIDDEN + n0 + tx];
    __syncthreads();
#pragma unroll
    for (int r = ty; r < 32; r += 8) {
        float f = t[tx][r];  // = W[k0+tx][n0+r]
        size_t idx = ((size_t)e * D_HIDDEN + n0 + r) * D_MODEL + k0 + tx;
        __nv_bfloat16 h = __float2bfloat16(f);
        g_whi[idx] = h;
        g_wlo[idx] = __float2bfloat16(f - __bfloat162float(h));
    }
}

// ---------------- mma.sync gathered GEMM ----------------
// smem: [0:512) rows_s | [512:1024) gates_s | [1024:) 2 stages x 32KB
//   stage: A_hi 8K | A_lo 8K | B_hi 8K | B_lo 8K   (tiles 128 rows x 32 bf16,
//   row = 64B = 4 x 16B chunks, chunk swizzle c' = c ^ ((row>>1)&3))
#define STAGE_B  32768
#define SMEM_DYN (1024 + 2 * STAGE_B)

template <int SLOT>
__global__ void __launch_bounds__(256, 2)
moe_gemm_mma(float* __restrict__ out) {
    const int e    = blockIdx.z;
    const int cnt  = g_counts[SLOT][e];
    const int row0 = blockIdx.y * BM;
    if (row0 >= cnt) return;
    const int n0  = blockIdx.x * BN;
    const int tid = threadIdx.x;

    extern __shared__ char smem[];
    int*   rows_s  = (int*)smem;
    float* gates_s = (float*)(smem + 512);
    const uint32_t sb    = smem_u32(smem);
    const uint32_t tiles = sb + 1024;

    if (tid < BM) {
        int idx = row0 + tid;
        if (idx < cnt) {
            rows_s[tid]  = g_bucket[SLOT][e][idx];
            gates_s[tid] = g_gate[SLOT][e][idx];
        } else {
            rows_s[tid]  = g_bucket[SLOT][e][row0];
            gates_s[tid] = 0.f;
        }
    }
    __syncthreads();

    const size_t wbase = ((size_t)e * D_HIDDEN + n0) * D_MODEL;

    // stage loader: 512 16B chunks per tile, 2 per thread per tile
    auto load_stage = [&](int i, int b) {
        const int kof = i * BK;
        const uint32_t st = tiles + b * STAGE_B;
#pragma unroll
        for (int q = 0; q < 2; q++) {
            const int ch = tid * 2 + q;
            const int r = ch >> 2, c = ch & 3;
            const uint32_t d = r * 64 + ((c ^ ((r >> 1) & 3)) << 4);
            const size_t asrc = (size_t)rows_s[r] * D_MODEL + kof + c * 8;
            cp16(st + d,         g_xhi + asrc);
            cp16(st + 8192 + d,  g_xlo + asrc);
            const size_t bsrc = wbase + (size_t)r * D_MODEL + kof + c * 8;
            cp16(st + 16384 + d, g_whi + bsrc);
            cp16(st + 24576 + d, g_wlo + bsrc);
        }
        CP_COMMIT();
    };

    // warp layout: 4 (M) x 2 (N); warp tile 32x64
    const int wid = tid >> 5, lane = tid & 31;
    const int wm = wid & 3, wn = wid >> 2;

    // per-lane ldmatrix address components
    // A (.x4): mat = lane>>3; row += (mat&1)*8; chunk += (mat>>1)
    uint32_t a_row[2], a_sw[2];
#pragma unroll
    for (int mt = 0; mt < 2; mt++) {
        const int m = wm * 32 + mt * 16 + ((lane >> 3) & 1) * 8 + (lane & 7);
        a_row[mt] = m * 64;
        a_sw[mt]  = (m >> 1) & 3;
    }
    const uint32_t a_hc = lane >> 4;          // chunk offset from mat>>1
    // B (.x4): mat0/1 = n rows, chunks c,c+1; mat2/3 = n+8 rows
    uint32_t b_row[4], b_sw[4];
#pragma unroll
    for (int p = 0; p < 4; p++) {
        const int n = wn * 64 + p * 16 + ((lane >> 4) & 1) * 8 + (lane & 7);
        b_row[p] = n * 64;
        b_sw[p]  = (n >> 1) & 3;
    }
    const uint32_t b_hc = (lane >> 3) & 1;    // chunk offset from mat&1

    float acc[2][8][4];
#pragma unroll
    for (int mt = 0; mt < 2; mt++)
#pragma unroll
        for (int nt = 0; nt < 8; nt++)
#pragma unroll
            for (int v = 0; v < 4; v++) acc[mt][nt][v] = 0.f;

    load_stage(0, 0);

    for (int i = 0; i < KCHUNKS; i++) {
        CP_WAIT0();
        __syncthreads();
        if (i + 1 < KCHUNKS) load_stage(i + 1, (i + 1) & 1);

        const uint32_t st = tiles + (i & 1) * STAGE_B;
#pragma unroll
        for (int pass = 0; pass < 3; pass++) {
            // pass 0: Ahi*Bhi, pass 1: Ahi*Blo, pass 2: Alo*Bhi
            const uint32_t Ab = st + (pass == 2 ? 8192 : 0);
            const uint32_t Bb = st + (pass == 1 ? 24576 : 16384);
#pragma unroll
            for (int kk = 0; kk < 2; kk++) {
                uint32_t a[2][4];
#pragma unroll
                for (int mt = 0; mt < 2; mt++)
                    ldsm4(a[mt], Ab + a_row[mt] +
                                 (((2 * kk + a_hc) ^ a_sw[mt]) << 4));
                uint32_t b[4][4];
#pragma unroll
                for (int p = 0; p < 4; p++)
                    ldsm4(b[p], Bb + b_row[p] +
                                (((2 * kk + b_hc) ^ b_sw[p]) << 4));
#pragma unroll
                for (int mt = 0; mt < 2; mt++)
#pragma unroll
                    for (int nt = 0; nt < 8; nt++)
                        mma_bf16(acc[mt][nt], a[mt],
                                 b[nt >> 1][(nt & 1) * 2],
                                 b[nt >> 1][(nt & 1) * 2 + 1]);
            }
        }
    }

    // epilogue: fragment (c0,c1)=row tg cols tc,tc+1; (c2,c3)=row tg+8
    const int tg = lane >> 2;
    const int tc = (lane & 3) * 2;
#pragma unroll
    for (int mt = 0; mt < 2; mt++) {
#pragma unroll
        for (int h = 0; h < 2; h++) {
            const int m = wm * 32 + mt * 16 + h * 8 + tg;
            if (row0 + m < cnt) {
                const int   token = rows_s[m];
                const float g     = gates_s[m];
                float* orow = out + (size_t)token * D_HIDDEN + n0 + wn * 64;
#pragma unroll
                for (int nt = 0; nt < 8; nt++) {
                    float* p = orow + nt * 8 + tc;
                    float vx = g * acc[mt][nt][h * 2];
                    float vy = g * acc[mt][nt][h * 2 + 1];
                    if (SLOT == 1) {
                        float2 old = *(float2*)p;
                        vx += old.x; vy += old.y;
                    }
                    *(float2*)p = make_float2(vx, vy);
                }
            }
        }
    }
}

// ---------------- launch ----------------
extern "C" void kernel_launch(void* const* d_in, const int* in_sizes, int n_in,
                              void* d_out, int out_size) {
    (void)in_sizes; (void)n_in; (void)out_size;
    const float* x  = (const float*)d_in[0];
    const float* rw = (const float*)d_in[1];
    const float* ew = (const float*)d_in[2];
    float* out = (float*)d_out;

    cudaFuncSetAttribute(moe_gemm_mma<0>,
                         cudaFuncAttributeMaxDynamicSharedMemorySize, SMEM_DYN);
    cudaFuncSetAttribute(moe_gemm_mma<1>,
                         cudaFuncAttributeMaxDynamicSharedMemorySize, SMEM_DYN);

    reset_kernel<<<1, 32>>>();
    router_kernel<<<N_TOKENS, 128>>>(x, rw);
    convert_x_kernel<<<(N_TOKENS * D_MODEL / 4) / 256, 256>>>(x);
    convert_w_kernel<<<dim3(D_HIDDEN / 32, D_MODEL / 32, NUM_EXPERTS),
                       dim3(32, 8)>>>(ew);

    dim3 grid(NTILES, N_TOKENS / BM, NUM_EXPERTS);  // (16, 64, 16), early-exit
    moe_gemm_mma<0><<<grid, 256, SMEM_DYN>>>(out);
    moe_gemm_mma<1><<<grid, 256, SMEM_DYN>>>(out);
}

// round 6
// speedup vs baseline: 3.0862x; 1.5363x over previous
#include <cuda_runtime.h>
#include <cuda_fp16.h>
#include <cstdint>

#define D_MODEL    2048
#define D_HIDDEN   2048
#define NUM_EXPERTS  16
#define N_TOKENS   8192

// mma.sync GEMM tile
#define BM 128
#define BN 128
#define BK 32
#define KCHUNKS (D_MODEL / BK)      // 64
#define NTILES  (D_HIDDEN / BN)     // 16

// ---------------- device scratch (no allocations allowed) ----------------
__device__ int   g_counts[2][NUM_EXPERTS];
__device__ int   g_bucket[2][NUM_EXPERTS][N_TOKENS];
__device__ float g_gate  [2][NUM_EXPERTS][N_TOKENS];

__device__ __half g_xf [(size_t)N_TOKENS * D_MODEL];             // x rounded to fp16
// W transposed to [e][n][k] (K contiguous), split hi/lo fp16
__device__ __half g_whi[(size_t)NUM_EXPERTS * D_HIDDEN * D_MODEL];
__device__ __half g_wlo[(size_t)NUM_EXPERTS * D_HIDDEN * D_MODEL];

// ---------------- PTX helpers (compute_103-safe: no tcgen05) ----------------
__device__ __forceinline__ uint32_t smem_u32(const void* p) {
    uint32_t a;
    asm("{ .reg .u64 t; cvta.to.shared.u64 t, %1; cvt.u32.u64 %0, t; }"
        : "=r"(a) : "l"(p));
    return a;
}
__device__ __forceinline__ void cp16(uint32_t dst, const void* src) {
    asm volatile("cp.async.cg.shared.global [%0], [%1], 16;\n"
                 :: "r"(dst), "l"(src));
}
#define CP_COMMIT() asm volatile("cp.async.commit_group;" ::: "memory")
#define CP_WAIT0()  asm volatile("cp.async.wait_group 0;" ::: "memory")

__device__ __forceinline__ void ldsm4(uint32_t* r, uint32_t addr) {
    asm volatile("ldmatrix.sync.aligned.m8n8.x4.shared.b16 {%0,%1,%2,%3}, [%4];"
                 : "=r"(r[0]), "=r"(r[1]), "=r"(r[2]), "=r"(r[3]) : "r"(addr));
}
__device__ __forceinline__ void mma_fp16(float* d, const uint32_t* a,
                                         uint32_t b0, uint32_t b1) {
    asm volatile(
        "mma.sync.aligned.m16n8k16.row.col.f32.f16.f16.f32 "
        "{%0,%1,%2,%3}, {%4,%5,%6,%7}, {%8,%9}, {%0,%1,%2,%3};"
        : "+f"(d[0]), "+f"(d[1]), "+f"(d[2]), "+f"(d[3])
        : "r"(a[0]), "r"(a[1]), "r"(a[2]), "r"(a[3]), "r"(b0), "r"(b1));
}

// ---------------- small kernels ----------------
__global__ void reset_kernel() {
    if (threadIdx.x < 2 * NUM_EXPERTS)
        ((int*)g_counts)[threadIdx.x] = 0;
}

__global__ void router_kernel(const float* __restrict__ x,
                              const float* __restrict__ rw) {
    __shared__ float sx[D_MODEL];
    __shared__ float slog[NUM_EXPERTS];
    const int token = blockIdx.x;
    const int tid   = threadIdx.x;   // 128
    const float4* xr = (const float4*)(x + (size_t)token * D_MODEL);
    for (int i = tid; i < D_MODEL / 4; i += 128)
        ((float4*)sx)[i] = xr[i];
    __syncthreads();

    const int warp = tid >> 5, lane = tid & 31;
    for (int e = warp; e < NUM_EXPERTS; e += 4) {
        const float* w = rw + (size_t)e * D_MODEL;
        float s = 0.f;
#pragma unroll 8
        for (int i = lane; i < D_MODEL; i += 32)
            s += sx[i] * __ldg(w + i);
#pragma unroll
        for (int o = 16; o > 0; o >>= 1)
            s += __shfl_xor_sync(0xffffffffu, s, o);
        if (lane == 0) slog[e] = s;
    }
    __syncthreads();

    if (tid == 0) {
        float l0 = -3.4e38f, l1 = -3.4e38f;
        int e0 = 0, e1 = 0;
#pragma unroll
        for (int e = 0; e < NUM_EXPERTS; e++) {
            float v = slog[e];
            if (v > l0)      { l1 = l0; e1 = e0; l0 = v; e0 = e; }
            else if (v > l1) { l1 = v;  e1 = e; }
        }
        float g0 = 1.f / (1.f + expf(l1 - l0));
        float g1 = 1.f - g0;
        int p0 = atomicAdd(&g_counts[0][e0], 1);
        g_bucket[0][e0][p0] = token;
        g_gate  [0][e0][p0] = g0;
        int p1 = atomicAdd(&g_counts[1][e1], 1);
        g_bucket[1][e1][p1] = token;
        g_gate  [1][e1][p1] = g1;
    }
}

// fp32 -> fp16 round of x (K-major)
__global__ void convert_x_kernel(const float* __restrict__ x) {
    size_t i = (size_t)blockIdx.x * blockDim.x + threadIdx.x;  // one float4
    float4 v = ((const float4*)x)[i];
    __half2* d = (__half2*)g_xf;
    d[2 * i]     = __floats2half2_rn(v.x, v.y);
    d[2 * i + 1] = __floats2half2_rn(v.z, v.w);
}

// W [e][k][n] fp32  ->  transposed fp16 hi/lo [e][n][k]
__global__ void convert_w_kernel(const float* __restrict__ W) {
    __shared__ float t[32][33];
    const int e  = blockIdx.z;
    const int k0 = blockIdx.y * 32;
    const int n0 = blockIdx.x * 32;
    const int tid = threadIdx.x;        // 256
    const float* src = W + (size_t)e * D_MODEL * D_HIDDEN;

    // load 32x32 fp32 tile: one float4 per thread
    {
        const int r  = tid >> 3;        // 0..31 (k)
        const int c4 = tid & 7;         // 0..7  (n group of 4)
        float4 v = *(const float4*)&src[(size_t)(k0 + r) * D_HIDDEN + n0 + c4 * 4];
        t[r][c4 * 4 + 0] = v.x;
        t[r][c4 * 4 + 1] = v.y;
        t[r][c4 * 4 + 2] = v.z;
        t[r][c4 * 4 + 3] = v.w;
    }
    __syncthreads();

    // write: thread handles (n, 4 consecutive k) -> two 8B packed stores
    {
        const int n  = tid >> 3;        // 0..31
        const int kg = tid & 7;         // 0..7 -> k = kg*4..+3
        float f[4];
#pragma unroll
        for (int j = 0; j < 4; j++) f[j] = t[kg * 4 + j][n];
        __half h[4], l[4];
#pragma unroll
        for (int j = 0; j < 4; j++) {
            h[j] = __float2half_rn(f[j]);
            l[j] = __float2half_rn(f[j] - __half2float(h[j]));
        }
        size_t idx = ((size_t)e * D_HIDDEN + n0 + n) * D_MODEL + k0 + kg * 4;
        __half2 ph0 = {h[0], h[1]}, ph1 = {h[2], h[3]};
        __half2 pl0 = {l[0], l[1]}, pl1 = {l[2], l[3]};
        *(__half2*)&g_whi[idx]     = ph0;
        *(__half2*)&g_whi[idx + 2] = ph1;
        *(__half2*)&g_wlo[idx]     = pl0;
        *(__half2*)&g_wlo[idx + 2] = pl1;
    }
}

// ---------------- mma.sync gathered GEMM (fp16 2-pass) ----------------
// smem: [0:512) rows_s | [512:1024) gates_s | [1024:) 2 stages x 24KB
//   stage: A 8K | B_hi 8K | B_lo 8K   (tiles 128 rows x 32 fp16,
//   row = 64B = 4 x 16B chunks, chunk swizzle c' = c ^ ((row>>1)&3))
#define STAGE_B  24576
#define SMEM_DYN (1024 + 2 * STAGE_B)

template <int SLOT>
__global__ void __launch_bounds__(256, 2)
moe_gemm_mma(float* __restrict__ out) {
    const int e    = blockIdx.z;
    const int cnt  = g_counts[SLOT][e];
    const int row0 = blockIdx.y * BM;
    if (row0 >= cnt) return;
    const int n0  = blockIdx.x * BN;
    const int tid = threadIdx.x;

    extern __shared__ char smem[];
    int*   rows_s  = (int*)smem;
    float* gates_s = (float*)(smem + 512);
    const uint32_t sb    = smem_u32(smem);
    const uint32_t tiles = sb + 1024;

    if (tid < BM) {
        int idx = row0 + tid;
        if (idx < cnt) {
            rows_s[tid]  = g_bucket[SLOT][e][idx];
            gates_s[tid] = g_gate[SLOT][e][idx];
        } else {
            rows_s[tid]  = g_bucket[SLOT][e][row0];
            gates_s[tid] = 0.f;
        }
    }
    __syncthreads();

    const size_t wbase = ((size_t)e * D_HIDDEN + n0) * D_MODEL;

    // stage loader: 3 x 512 16B chunks, 2 chunk-slots per thread
    auto load_stage = [&](int i, int b) {
        const int kof = i * BK;
        const uint32_t st = tiles + b * STAGE_B;
#pragma unroll
        for (int q = 0; q < 2; q++) {
            const int ch = tid * 2 + q;
            const int r = ch >> 2, c = ch & 3;
            const uint32_t d = r * 64 + ((c ^ ((r >> 1) & 3)) << 4);
            const size_t asrc = (size_t)rows_s[r] * D_MODEL + kof + c * 8;
            cp16(st + d, g_xf + asrc);
            const size_t bsrc = wbase + (size_t)r * D_MODEL + kof + c * 8;
            cp16(st + 8192  + d, g_whi + bsrc);
            cp16(st + 16384 + d, g_wlo + bsrc);
        }
        CP_COMMIT();
    };

    // warp layout: 4 (M) x 2 (N); warp tile 32x64
    const int wid = tid >> 5, lane = tid & 31;
    const int wm = wid & 3, wn = wid >> 2;

    // per-lane ldmatrix address components
    uint32_t a_row[2], a_sw[2];
#pragma unroll
    for (int mt = 0; mt < 2; mt++) {
        const int m = wm * 32 + mt * 16 + ((lane >> 3) & 1) * 8 + (lane & 7);
        a_row[mt] = m * 64;
        a_sw[mt]  = (m >> 1) & 3;
    }
    const uint32_t a_hc = lane >> 4;
    uint32_t b_row[4], b_sw[4];
#pragma unroll
    for (int p = 0; p < 4; p++) {
        const int n = wn * 64 + p * 16 + ((lane >> 4) & 1) * 8 + (lane & 7);
        b_row[p] = n * 64;
        b_sw[p]  = (n >> 1) & 3;
    }
    const uint32_t b_hc = (lane >> 3) & 1;

    float acc[2][8][4];
#pragma unroll
    for (int mt = 0; mt < 2; mt++)
#pragma unroll
        for (int nt = 0; nt < 8; nt++)
#pragma unroll
            for (int v = 0; v < 4; v++) acc[mt][nt][v] = 0.f;

    load_stage(0, 0);

    for (int i = 0; i < KCHUNKS; i++) {
        CP_WAIT0();
        __syncthreads();
        if (i + 1 < KCHUNKS) load_stage(i + 1, (i + 1) & 1);

        const uint32_t st = tiles + (i & 1) * STAGE_B;
#pragma unroll
        for (int kk = 0; kk < 2; kk++) {
            // A fragments loaded once, reused for both B passes
            uint32_t a[2][4];
#pragma unroll
            for (int mt = 0; mt < 2; mt++)
                ldsm4(a[mt], st + a_row[mt] +
                             (((2 * kk + a_hc) ^ a_sw[mt]) << 4));
            uint32_t bh[4][4];
#pragma unroll
            for (int p = 0; p < 4; p++)
                ldsm4(bh[p], st + 8192 + b_row[p] +
                             (((2 * kk + b_hc) ^ b_sw[p]) << 4));
#pragma unroll
            for (int mt = 0; mt < 2; mt++)
#pragma unroll
                for (int nt = 0; nt < 8; nt++)
                    mma_fp16(acc[mt][nt], a[mt],
                             bh[nt >> 1][(nt & 1) * 2],
                             bh[nt >> 1][(nt & 1) * 2 + 1]);
            uint32_t bl[4][4];
#pragma unroll
            for (int p = 0; p < 4; p++)
                ldsm4(bl[p], st + 16384 + b_row[p] +
                             (((2 * kk + b_hc) ^ b_sw[p]) << 4));
#pragma unroll
            for (int mt = 0; mt < 2; mt++)
#pragma unroll
                for (int nt = 0; nt < 8; nt++)
                    mma_fp16(acc[mt][nt], a[mt],
                             bl[nt >> 1][(nt & 1) * 2],
                             bl[nt >> 1][(nt & 1) * 2 + 1]);
        }
    }

    // epilogue
    const int tg = lane >> 2;
    const int tc = (lane & 3) * 2;
#pragma unroll
    for (int mt = 0; mt < 2; mt++) {
#pragma unroll
        for (int h = 0; h < 2; h++) {
            const int m = wm * 32 + mt * 16 + h * 8 + tg;
            if (row0 + m < cnt) {
                const int   token = rows_s[m];
                const float g     = gates_s[m];
                float* orow = out + (size_t)token * D_HIDDEN + n0 + wn * 64;
#pragma unroll
                for (int nt = 0; nt < 8; nt++) {
                    float* p = orow + nt * 8 + tc;
                    float vx = g * acc[mt][nt][h * 2];
                    float vy = g * acc[mt][nt][h * 2 + 1];
                    if (SLOT == 1) {
                        float2 old = *(float2*)p;
                        vx += old.x; vy += old.y;
                    }
                    *(float2*)p = make_float2(vx, vy);
                }
            }
        }
    }
}

// ---------------- launch ----------------
extern "C" void kernel_launch(void* const* d_in, const int* in_sizes, int n_in,
                              void* d_out, int out_size) {
    (void)in_sizes; (void)n_in; (void)out_size;
    const float* x  = (const float*)d_in[0];
    const float* rw = (const float*)d_in[1];
    const float* ew = (const float*)d_in[2];
    float* out = (float*)d_out;

    cudaFuncSetAttribute(moe_gemm_mma<0>,
                         cudaFuncAttributeMaxDynamicSharedMemorySize, SMEM_DYN);
    cudaFuncSetAttribute(moe_gemm_mma<1>,
                         cudaFuncAttributeMaxDynamicSharedMemorySize, SMEM_DYN);

    reset_kernel<<<1, 32>>>();
    router_kernel<<<N_TOKENS, 128>>>(x, rw);
    convert_x_kernel<<<(N_TOKENS * D_MODEL / 4) / 256, 256>>>(x);
    convert_w_kernel<<<dim3(D_HIDDEN / 32, D_MODEL / 32, NUM_EXPERTS),
                       dim3(256)>>>(ew);

    dim3 grid(NTILES, N_TOKENS / BM, NUM_EXPERTS);  // (16, 64, 16), early-exit
    moe_gemm_mma<0><<<grid, 256, SMEM_DYN>>>(out);
    moe_gemm_mma<1><<<grid, 256, SMEM_DYN>>>(out);
}

// round 8
// speedup vs baseline: 4.4863x; 1.4537x over previous
#include <cuda_runtime.h>
#include <cuda_fp16.h>
#include <cstdint>

#define D_MODEL    2048
#define D_HIDDEN   2048
#define NUM_EXPERTS  16
#define N_TOKENS   8192

// mma.sync GEMM tile
#define BM 128
#define BN 128
#define BK 32
#define KCHUNKS (D_MODEL / BK)      // 64
#define NTILES  (D_HIDDEN / BN)     // 16

// ---------------- device scratch (no allocations allowed) ----------------
__device__ int   g_counts[2][NUM_EXPERTS];
__device__ int   g_bucket[2][NUM_EXPERTS][N_TOKENS];
__device__ float g_gate  [2][NUM_EXPERTS][N_TOKENS];

__device__ __half g_xf[(size_t)N_TOKENS * D_MODEL];              // x -> fp16
// W transposed to [e][n][k] (K contiguous), rounded to fp16
__device__ __half g_wf[(size_t)NUM_EXPERTS * D_HIDDEN * D_MODEL];

// ---------------- PTX helpers (compute_103-safe: no tcgen05) ----------------
__device__ __forceinline__ uint32_t smem_u32(const void* p) {
    uint32_t a;
    asm("{ .reg .u64 t; cvta.to.shared.u64 t, %1; cvt.u32.u64 %0, t; }"
        : "=r"(a) : "l"(p));
    return a;
}
__device__ __forceinline__ void cp16(uint32_t dst, const void* src) {
    asm volatile("cp.async.cg.shared.global [%0], [%1], 16;\n"
                 :: "r"(dst), "l"(src));
}
#define CP_COMMIT() asm volatile("cp.async.commit_group;" ::: "memory")
#define CP_WAIT0()  asm volatile("cp.async.wait_group 0;" ::: "memory")

__device__ __forceinline__ void ldsm4(uint32_t* r, uint32_t addr) {
    asm volatile("ldmatrix.sync.aligned.m8n8.x4.shared.b16 {%0,%1,%2,%3}, [%4];"
                 : "=r"(r[0]), "=r"(r[1]), "=r"(r[2]), "=r"(r[3]) : "r"(addr));
}
__device__ __forceinline__ void mma_fp16(float* d, const uint32_t* a,
                                         uint32_t b0, uint32_t b1) {
    asm volatile(
        "mma.sync.aligned.m16n8k16.row.col.f32.f16.f16.f32 "
        "{%0,%1,%2,%3}, {%4,%5,%6,%7}, {%8,%9}, {%0,%1,%2,%3};"
        : "+f"(d[0]), "+f"(d[1]), "+f"(d[2]), "+f"(d[3])
        : "r"(a[0]), "r"(a[1]), "r"(a[2]), "r"(a[3]), "r"(b0), "r"(b1));
}

// ---------------- small kernels ----------------
__global__ void reset_kernel() {
    if (threadIdx.x < 2 * NUM_EXPERTS)
        ((int*)g_counts)[threadIdx.x] = 0;
}

__global__ void router_kernel(const float* __restrict__ x,
                              const float* __restrict__ rw) {
    __shared__ float sx[D_MODEL];
    __shared__ float slog[NUM_EXPERTS];
    const int token = blockIdx.x;
    const int tid   = threadIdx.x;   // 128
    const float4* xr = (const float4*)(x + (size_t)token * D_MODEL);
    for (int i = tid; i < D_MODEL / 4; i += 128)
        ((float4*)sx)[i] = xr[i];
    __syncthreads();

    const int warp = tid >> 5, lane = tid & 31;
    for (int e = warp; e < NUM_EXPERTS; e += 4) {
        const float* w = rw + (size_t)e * D_MODEL;
        float s = 0.f;
#pragma unroll 8
        for (int i = lane; i < D_MODEL; i += 32)
            s += sx[i] * __ldg(w + i);
#pragma unroll
        for (int o = 16; o > 0; o >>= 1)
            s += __shfl_xor_sync(0xffffffffu, s, o);
        if (lane == 0) slog[e] = s;
    }
    __syncthreads();

    if (tid == 0) {
        float l0 = -3.4e38f, l1 = -3.4e38f;
        int e0 = 0, e1 = 0;
#pragma unroll
        for (int e = 0; e < NUM_EXPERTS; e++) {
            float v = slog[e];
            if (v > l0)      { l1 = l0; e1 = e0; l0 = v; e0 = e; }
            else if (v > l1) { l1 = v;  e1 = e; }
        }
        float g0 = 1.f / (1.f + expf(l1 - l0));
        float g1 = 1.f - g0;
        int p0 = atomicAdd(&g_counts[0][e0], 1);
        g_bucket[0][e0][p0] = token;
        g_gate  [0][e0][p0] = g0;
        int p1 = atomicAdd(&g_counts[1][e1], 1);
        g_bucket[1][e1][p1] = token;
        g_gate  [1][e1][p1] = g1;
    }
}

// fp32 -> fp16 round of x (K-major)
__global__ void convert_x_kernel(const float* __restrict__ x) {
    size_t i = (size_t)blockIdx.x * blockDim.x + threadIdx.x;  // one float4
    float4 v = ((const float4*)x)[i];
    __half2* d = (__half2*)g_xf;
    d[2 * i]     = __floats2half2_rn(v.x, v.y);
    d[2 * i + 1] = __floats2half2_rn(v.z, v.w);
}

// W [e][k][n] fp32  ->  transposed fp16 [e][n][k]
__global__ void convert_w_kernel(const float* __restrict__ W) {
    __shared__ float t[32][33];
    const int e  = blockIdx.z;
    const int k0 = blockIdx.y * 32;
    const int n0 = blockIdx.x * 32;
    const int tid = threadIdx.x;        // 256
    const float* src = W + (size_t)e * D_MODEL * D_HIDDEN;

    // load 32x32 fp32 tile: one float4 per thread
    {
        const int r  = tid >> 3;        // 0..31 (k)
        const int c4 = tid & 7;         // 0..7  (n group of 4)
        float4 v = *(const float4*)&src[(size_t)(k0 + r) * D_HIDDEN + n0 + c4 * 4];
        t[r][c4 * 4 + 0] = v.x;
        t[r][c4 * 4 + 1] = v.y;
        t[r][c4 * 4 + 2] = v.z;
        t[r][c4 * 4 + 3] = v.w;
    }
    __syncthreads();

    // write: thread handles (n, 4 consecutive k) -> one 8B packed store
    {
        const int n  = tid >> 3;        // 0..31
        const int kg = tid & 7;         // 0..7 -> k = kg*4..+3
        float f[4];
#pragma unroll
        for (int j = 0; j < 4; j++) f[j] = t[kg * 4 + j][n];
        __half2 p0 = __floats2half2_rn(f[0], f[1]);
        __half2 p1 = __floats2half2_rn(f[2], f[3]);
        size_t idx = ((size_t)e * D_HIDDEN + n0 + n) * D_MODEL + k0 + kg * 4;
        *(__half2*)&g_wf[idx]     = p0;
        *(__half2*)&g_wf[idx + 2] = p1;
    }
}

// ---------------- mma.sync gathered GEMM (fp16 single pass) ----------------
// smem: [0:512) rows_s | [512:1024) gates_s | [1024:) 2 stages x 16KB
//   stage: A 8K | B 8K   (tiles 128 rows x 32 fp16,
//   row = 64B = 4 x 16B chunks, chunk swizzle c' = c ^ ((row>>1)&3))
#define STAGE_B  16384
#define SMEM_DYN (1024 + 2 * STAGE_B)

template <int SLOT>
__global__ void __launch_bounds__(256, 2)
moe_gemm_mma(float* __restrict__ out) {
    const int e    = blockIdx.z;
    const int cnt  = g_counts[SLOT][e];
    const int row0 = blockIdx.y * BM;
    if (row0 >= cnt) return;
    const int n0  = blockIdx.x * BN;
    const int tid = threadIdx.x;

    extern __shared__ char smem[];
    int*   rows_s  = (int*)smem;
    float* gates_s = (float*)(smem + 512);
    const uint32_t sb    = smem_u32(smem);
    const uint32_t tiles = sb + 1024;

    if (tid < BM) {
        int idx = row0 + tid;
        if (idx < cnt) {
            rows_s[tid]  = g_bucket[SLOT][e][idx];
            gates_s[tid] = g_gate[SLOT][e][idx];
        } else {
            rows_s[tid]  = g_bucket[SLOT][e][row0];
            gates_s[tid] = 0.f;
        }
    }
    __syncthreads();

    const size_t wbase = ((size_t)e * D_HIDDEN + n0) * D_MODEL;

    // stage loader: 2 x 512 16B chunks, 2 chunk-slots per thread
    auto load_stage = [&](int i, int b) {
        const int kof = i * BK;
        const uint32_t st = tiles + b * STAGE_B;
#pragma unroll
        for (int q = 0; q < 2; q++) {
            const int ch = tid * 2 + q;
            const int r = ch >> 2, c = ch & 3;
            const uint32_t d = r * 64 + ((c ^ ((r >> 1) & 3)) << 4);
            const size_t asrc = (size_t)rows_s[r] * D_MODEL + kof + c * 8;
            cp16(st + d, g_xf + asrc);
            const size_t bsrc = wbase + (size_t)r * D_MODEL + kof + c * 8;
            cp16(st + 8192 + d, g_wf + bsrc);
        }
        CP_COMMIT();
    };

    // warp layout: 4 (M) x 2 (N); warp tile 32x64
    const int wid = tid >> 5, lane = tid & 31;
    const int wm = wid & 3, wn = wid >> 2;

    // per-lane ldmatrix address components
    uint32_t a_row[2], a_sw[2];
#pragma unroll
    for (int mt = 0; mt < 2; mt++) {
        const int m = wm * 32 + mt * 16 + ((lane >> 3) & 1) * 8 + (lane & 7);
        a_row[mt] = m * 64;
        a_sw[mt]  = (m >> 1) & 3;
    }
    const uint32_t a_hc = lane >> 4;
    uint32_t b_row[4], b_sw[4];
#pragma unroll
    for (int p = 0; p < 4; p++) {
        const int n = wn * 64 + p * 16 + ((lane >> 4) & 1) * 8 + (lane & 7);
        b_row[p] = n * 64;
        b_sw[p]  = (n >> 1) & 3;
    }
    const uint32_t b_hc = (lane >> 3) & 1;

    float acc[2][8][4];
#pragma unroll
    for (int mt = 0; mt < 2; mt++)
#pragma unroll
        for (int nt = 0; nt < 8; nt++)
#pragma unroll
            for (int v = 0; v < 4; v++) acc[mt][nt][v] = 0.f;

    load_stage(0, 0);

    for (int i = 0; i < KCHUNKS; i++) {
        CP_WAIT0();
        __syncthreads();
        if (i + 1 < KCHUNKS) load_stage(i + 1, (i + 1) & 1);

        const uint32_t st = tiles + (i & 1) * STAGE_B;
#pragma unroll
        for (int kk = 0; kk < 2; kk++) {
            uint32_t a[2][4];
#pragma unroll
            for (int mt = 0; mt < 2; mt++)
                ldsm4(a[mt], st + a_row[mt] +
                             (((2 * kk + a_hc) ^ a_sw[mt]) << 4));
            uint32_t b[4][4];
#pragma unroll
            for (int p = 0; p < 4; p++)
                ldsm4(b[p], st + 8192 + b_row[p] +
                            (((2 * kk + b_hc) ^ b_sw[p]) << 4));
#pragma unroll
            for (int mt = 0; mt < 2; mt++)
#pragma unroll
                for (int nt = 0; nt < 8; nt++)
                    mma_fp16(acc[mt][nt], a[mt],
                             b[nt >> 1][(nt & 1) * 2],
                             b[nt >> 1][(nt & 1) * 2 + 1]);
        }
    }

    // epilogue
    const int tg = lane >> 2;
    const int tc = (lane & 3) * 2;
#pragma unroll
    for (int mt = 0; mt < 2; mt++) {
#pragma unroll
        for (int h = 0; h < 2; h++) {
            const int m = wm * 32 + mt * 16 + h * 8 + tg;
            if (row0 + m < cnt) {
                const int   token = rows_s[m];
                const float g     = gates_s[m];
                float* orow = out + (size_t)token * D_HIDDEN + n0 + wn * 64;
#pragma unroll
                for (int nt = 0; nt < 8; nt++) {
                    float* p = orow + nt * 8 + tc;
                    float vx = g * acc[mt][nt][h * 2];
                    float vy = g * acc[mt][nt][h * 2 + 1];
                    if (SLOT == 1) {
                        float2 old = *(float2*)p;
                        vx += old.x; vy += old.y;
                    }
                    *(float2*)p = make_float2(vx, vy);
                }
            }
        }
    }
}

// ---------------- launch ----------------
extern "C" void kernel_launch(void* const* d_in, const int* in_sizes, int n_in,
                              void* d_out, int out_size) {
    (void)in_sizes; (void)n_in; (void)out_size;
    const float* x  = (const float*)d_in[0];
    const float* rw = (const float*)d_in[1];
    const float* ew = (const float*)d_in[2];
    float* out = (float*)d_out;

    cudaFuncSetAttribute(moe_gemm_mma<0>,
                         cudaFuncAttributeMaxDynamicSharedMemorySize, SMEM_DYN);
    cudaFuncSetAttribute(moe_gemm_mma<1>,
                         cudaFuncAttributeMaxDynamicSharedMemorySize, SMEM_DYN);

    reset_kernel<<<1, 32>>>();
    router_kernel<<<N_TOKENS, 128>>>(x, rw);
    convert_x_kernel<<<(N_TOKENS * D_MODEL / 4) / 256, 256>>>(x);
    convert_w_kernel<<<dim3(D_HIDDEN / 32, D_MODEL / 32, NUM_EXPERTS),
                       dim3(256)>>>(ew);

    dim3 grid(NTILES, N_TOKENS / BM, NUM_EXPERTS);  // (16, 64, 16), early-exit
    moe_gemm_mma<0><<<grid, 256, SMEM_DYN>>>(out);
    moe_gemm_mma<1><<<grid, 256, SMEM_DYN>>>(out);
}